// round 5
// baseline (speedup 1.0000x reference)
#include <cuda_runtime.h>
#include <cstdint>

#define N_NODES 12288
#define H_DIM   128
#define E_EDGES 393216
#define NEGVAL  (-1000000000.0f)
#define ROW4    (N_NODES / 4)      // 3072 float4 per row
#define CAP     256                // bucket capacity per row (Poisson(32), max~65)

// Static scratch (no cudaMalloc allowed). g_cursor is zero-init at module
// load and self-restored to zero by fill_merge_kernel every launch.
__device__ float g_d1[N_NODES];
__device__ float g_d2[N_NODES];
__device__ int   g_cursor[N_NODES];
__device__ int2  g_bucket[(size_t)N_NODES * CAP];   // (src_col, float_bits(weight))

// ---------------------------------------------------------------------------
// A: per-node dots (1 warp/node; grid has exactly N warps) + edge placement
//    (1 thread/edge). Placement stores only (src, weight) -> no dependency
//    on the dots, so both live in one kernel.
// ---------------------------------------------------------------------------
__global__ void dots_place_kernel(const float* __restrict__ h,
                                  const float* __restrict__ W,
                                  const int*   __restrict__ src,
                                  const int*   __restrict__ dst,
                                  const float* __restrict__ wts) {
    int t    = (int)(blockIdx.x * blockDim.x + threadIdx.x);
    int gw   = t >> 5;
    int lane = t & 31;

    // ---- edge placement (independent loads first, then atomic+store) ----
    int   s  = src[t];
    int   d  = dst[t];
    float w  = wts[t];

    // ---- dots: warp gw handles node gw (E/32 == N exactly) ----
    {
        const float4* hr4 = (const float4*)(h + (size_t)gw * H_DIM);
        const float4* w14 = (const float4*)(W);
        const float4* w24 = (const float4*)(W + H_DIM);
        float4 hv = __ldg(&hr4[lane]);
        float4 w1 = __ldg(&w14[lane]);
        float4 w2 = __ldg(&w24[lane]);
        float s1 = fmaf(hv.x, w1.x, fmaf(hv.y, w1.y, fmaf(hv.z, w1.z, hv.w * w1.w)));
        float s2 = fmaf(hv.x, w2.x, fmaf(hv.y, w2.y, fmaf(hv.z, w2.z, hv.w * w2.w)));
#pragma unroll
        for (int off = 16; off; off >>= 1) {
            s1 += __shfl_down_sync(0xffffffffu, s1, off);
            s2 += __shfl_down_sync(0xffffffffu, s2, off);
        }
        if (lane == 0) { g_d1[gw] = s1; g_d2[gw] = s2; }
    }

    // finish placement
    int pos = atomicAdd(&g_cursor[d], 1);
    if (pos < CAP) {
        g_bucket[(size_t)d * CAP + pos] = make_int2(s, __float_as_int(w));
    }
}

// ---------------------------------------------------------------------------
// D: fill + merge + cursor reset. Build each 48KB row in static smem
//    (NEG + this row's edge values), stream it out with __stcs. DRAM sees
//    only one sequential 604MB write stream — no random row activations.
//    val = d1[row] + d2[src] + fma(weight, W[2H], b); gathers are L2-hot.
// ---------------------------------------------------------------------------
__global__ __launch_bounds__(512) void fill_merge_kernel(
        float4* __restrict__ out,
        const float* __restrict__ W,
        const float* __restrict__ b) {
    __shared__ float row[N_NODES];               // exactly 48 KB
    __shared__ int   s_cnt;
    float4* row4 = (float4*)row;
    const float4 v = make_float4(NEGVAL, NEGVAL, NEGVAL, NEGVAL);

    const float wlin = __ldg(&W[2 * H_DIM]);
    const float bias = __ldg(&b[0]);

    for (int r = blockIdx.x; r < N_NODES; r += gridDim.x) {
#pragma unroll
        for (int i = threadIdx.x; i < ROW4; i += 512) row4[i] = v;

        if (threadIdx.x == 0) {
            int c = g_cursor[r];
            s_cnt = (c < CAP) ? c : CAP;
            g_cursor[r] = 0;                     // self-restore for next launch
        }
        __syncthreads();

        int   cnt = s_cnt;
        float d1r = g_d1[r];
        const int2* bkt = &g_bucket[(size_t)r * CAP];
        for (int i = (int)threadIdx.x; i < cnt; i += 512) {
            int2  ev  = bkt[i];
            float val = d1r + g_d2[ev.x] + fmaf(__int_as_float(ev.y), wlin, bias);
            row[ev.x] = val;                     // dup races benign
        }
        __syncthreads();

        float4* dstp = out + (size_t)r * ROW4;
#pragma unroll
        for (int i = threadIdx.x; i < ROW4; i += 512) __stcs(&dstp[i], row4[i]);
        __syncthreads();                          // before smem reuse
    }
}

// ---------------------------------------------------------------------------
// Launch. Input order (metadata): h, sources, dests, weights, W, b
// ---------------------------------------------------------------------------
extern "C" void kernel_launch(void* const* d_in, const int* in_sizes, int n_in,
                              void* d_out, int out_size) {
    const float* h       = (const float*)d_in[0];
    const int*   sources = (const int*)  d_in[1];
    const int*   dests   = (const int*)  d_in[2];
    const float* weights = (const float*)d_in[3];
    const float* W       = (const float*)d_in[4];
    const float* b       = (const float*)d_in[5];
    float*       out     = (float*)d_out;

    // A: dots + edge placement. E threads; warp i == node i.
    dots_place_kernel<<<E_EDGES / 256, 256>>>(h, W, sources, dests, weights);

    // D: fill + merge + cursor reset. One wave of 4 blocks/SM.
    fill_merge_kernel<<<148 * 4, 512>>>((float4*)out, W, b);
}